// round 17
// baseline (speedup 1.0000x reference)
#include <cuda_runtime.h>
#include <cuda_bf16.h>
#include <cuda_fp16.h>
#include <math_constants.h>

#define N_NODES 50000
#define N_EDGES 800000
#define DOUT 128

// scratch (device globals — no allocation allowed)
__device__ __half g_h16[(size_t)N_NODES * DOUT];   // 12.8 MB (L2-resident)
__device__ float g_sdst[N_NODES];
__device__ float g_ssrc[N_NODES];
__device__ int   g_rowptr[N_NODES + 1];

// ---------------------------------------------------------------------------
// helpers
// ---------------------------------------------------------------------------
__device__ __forceinline__ unsigned long long pk2(float lo, float hi) {
    unsigned long long r;
    asm("mov.b64 %0, {%1, %2};" : "=l"(r) : "f"(lo), "f"(hi));
    return r;
}
__device__ __forceinline__ void upk2(unsigned long long v, float& lo, float& hi) {
    asm("mov.b64 {%0, %1}, %2;" : "=f"(lo), "=f"(hi) : "l"(v));
}
__device__ __forceinline__ void ffma2(unsigned long long& d,
                                      unsigned long long a, unsigned long long b) {
    asm("fma.rn.f32x2 %0, %1, %2, %0;" : "+l"(d) : "l"(a), "l"(b));
}
__device__ __forceinline__ unsigned sptr(const void* p) {
    return (unsigned)__cvta_generic_to_shared(p);
}
__device__ __forceinline__ unsigned pack_bf2(float a, float b) {
    __nv_bfloat162 t = __floats2bfloat162_rn(a, b);
    return *(unsigned*)&t;
}
__device__ __forceinline__ void ldsm_x4(unsigned addr, unsigned& r0, unsigned& r1,
                                        unsigned& r2, unsigned& r3) {
    asm volatile("ldmatrix.sync.aligned.m8n8.x4.shared.b16 {%0,%1,%2,%3}, [%4];"
                 : "=r"(r0), "=r"(r1), "=r"(r2), "=r"(r3) : "r"(addr));
}
__device__ __forceinline__ void ldsm_x2t(unsigned addr, unsigned& r0, unsigned& r1) {
    asm volatile("ldmatrix.sync.aligned.m8n8.x2.trans.shared.b16 {%0,%1}, [%2];"
                 : "=r"(r0), "=r"(r1) : "r"(addr));
}
__device__ __forceinline__ void mma_bf16(float* c, unsigned a0, unsigned a1,
                                         unsigned a2, unsigned a3,
                                         unsigned b0, unsigned b1) {
    asm volatile(
        "mma.sync.aligned.m16n8k16.row.col.f32.bf16.bf16.f32 "
        "{%0,%1,%2,%3}, {%4,%5,%6,%7}, {%8,%9}, {%0,%1,%2,%3};\n"
        : "+f"(c[0]), "+f"(c[1]), "+f"(c[2]), "+f"(c[3])
        : "r"(a0), "r"(a1), "r"(a2), "r"(a3), "r"(b0), "r"(b1));
}

// ---------------------------------------------------------------------------
// K1: PERSISTENT fused GEMM + scores. bf16x2 (3-term) tensor-core GEMM.
//     512 threads (16 warps, 4M x 4N, 32x32 warp tiles), 128x128 block tile.
//     Double-buffered X stages; 1 sync per k-subtile; cross-tile prefetch.
// ---------------------------------------------------------------------------
#define WROW 136   // bf16 per W smem row (128 + 8 pad)
#define XROW 40    // bf16 per X smem row (32 + 8 pad)
#define NTILES ((N_NODES + 127) / 128)
#define XSTAGE (128 * XROW)          // bf16 elems per stage (10240 B)

__global__ __launch_bounds__(512) void gemm_score_kernel(
    const float* __restrict__ x, const float* __restrict__ W,
    const float* __restrict__ b, const float* __restrict__ a_w, int N)
{
    extern __shared__ char smem[];
    __nv_bfloat16* Whi = (__nv_bfloat16*)smem;                 // [128][WROW]
    __nv_bfloat16* Wlo = (__nv_bfloat16*)(smem + 34816);
    __nv_bfloat16* Xhi = (__nv_bfloat16*)(smem + 69632);       // [2][128][XROW]
    __nv_bfloat16* Xlo = (__nv_bfloat16*)(smem + 90112);       // [2][128][XROW]
    float* sPartD = (float*)(smem + 110592);                   // [4][128]
    float* sPartS = (float*)(smem + 112640);                   // [4][128]

    const int tid  = threadIdx.x;
    const int wid  = tid >> 5;
    const int lane = tid & 31;

    const int warpM = (wid >> 2) * 32;
    const int warpN = (wid & 3) * 32;

    // ---- once per block: convert W (fp32 [k][n]) -> smem bf16 hi/lo ----
    #pragma unroll
    for (int it = 0; it < 4; ++it) {
        int idx8 = tid + it * 512;           // 0..2047
        int k   = idx8 >> 4;
        int n8  = (idx8 & 15) * 8;
        const float4* wp = (const float4*)(W + (size_t)k * 128 + n8);
        float4 f0 = wp[0], f1 = wp[1];
        float vf[8] = {f0.x, f0.y, f0.z, f0.w, f1.x, f1.y, f1.z, f1.w};
        unsigned hiw[4], low[4];
        #pragma unroll
        for (int p = 0; p < 4; ++p) {
            float va = vf[p * 2], vb = vf[p * 2 + 1];
            __nv_bfloat16 ha = __float2bfloat16_rn(va);
            __nv_bfloat16 hb = __float2bfloat16_rn(vb);
            hiw[p] = pack_bf2(__bfloat162float(ha), __bfloat162float(hb));
            low[p] = pack_bf2(va - __bfloat162float(ha), vb - __bfloat162float(hb));
        }
        *(uint4*)(Whi + (size_t)k * WROW + n8) = *(uint4*)hiw;
        *(uint4*)(Wlo + (size_t)k * WROW + n8) = *(uint4*)low;
    }

    // per-thread constant maps
    const int lx_row = tid >> 2;              // 0..127
    const int lx_kb  = (tid & 3) * 8;         // 0,8,16,24
    const unsigned a_off = (unsigned)((warpM + (lane & 15)) * XROW + (lane >> 4) * 8) * 2;
    const unsigned xhi_s = sptr(Xhi);
    const unsigned xlo_s = sptr(Xlo);
    const int g   = lane >> 2;
    const int tig = lane & 3;

    const int tile0 = blockIdx.x;

    float4 fx[2];
    {   // prefetch (tile0, subtile 0)
        int grow = tile0 * 128 + lx_row;
        if (grow < N) {
            const float* xp = x + (size_t)grow * 128 + lx_kb;
            fx[0] = *(const float4*)xp;
            fx[1] = *(const float4*)(xp + 4);
        } else {
            fx[0] = fx[1] = make_float4(0.f, 0.f, 0.f, 0.f);
        }
    }

    for (int tile = tile0; tile < NTILES; tile += gridDim.x) {
        const int rowBase = tile * 128;

        float c[2][4][4];
        #pragma unroll
        for (int mf = 0; mf < 2; ++mf)
            #pragma unroll
            for (int nf = 0; nf < 4; ++nf)
                #pragma unroll
                for (int r = 0; r < 4; ++r) c[mf][nf][r] = 0.f;

        #pragma unroll
        for (int t = 0; t < 4; ++t) {
            const int stage = t & 1;
            // ---- STS current subtile into its stage ----
            {
                float vf[8] = {fx[0].x, fx[0].y, fx[0].z, fx[0].w,
                               fx[1].x, fx[1].y, fx[1].z, fx[1].w};
                unsigned hiw[4], low[4];
                #pragma unroll
                for (int p = 0; p < 4; ++p) {
                    float va = vf[p * 2], vb = vf[p * 2 + 1];
                    __nv_bfloat16 ha = __float2bfloat16_rn(va);
                    __nv_bfloat16 hb = __float2bfloat16_rn(vb);
                    hiw[p] = pack_bf2(__bfloat162float(ha), __bfloat162float(hb));
                    low[p] = pack_bf2(va - __bfloat162float(ha), vb - __bfloat162float(hb));
                }
                size_t off = (size_t)stage * XSTAGE + (size_t)lx_row * XROW + lx_kb;
                *(uint4*)(Xhi + off) = *(uint4*)hiw;
                *(uint4*)(Xlo + off) = *(uint4*)low;
            }
            __syncthreads();

            // ---- prefetch next subtile (next tile's subtile 0 at t==3) ----
            if (t < 3) {
                int grow = rowBase + lx_row;
                if (grow < N) {
                    const float* xp = x + (size_t)grow * 128 + (t + 1) * 32 + lx_kb;
                    fx[0] = *(const float4*)xp;
                    fx[1] = *(const float4*)(xp + 4);
                } else {
                    fx[0] = fx[1] = make_float4(0.f, 0.f, 0.f, 0.f);
                }
            } else {
                int ntile = tile + gridDim.x;
                if (ntile < NTILES) {
                    int grow = ntile * 128 + lx_row;
                    if (grow < N) {
                        const float* xp = x + (size_t)grow * 128 + lx_kb;
                        fx[0] = *(const float4*)xp;
                        fx[1] = *(const float4*)(xp + 4);
                    } else {
                        fx[0] = fx[1] = make_float4(0.f, 0.f, 0.f, 0.f);
                    }
                }
            }

            // ---- compute this subtile (2 k16 steps) ----
            const unsigned aHi_base = xhi_s + stage * (XSTAGE * 2) + a_off;
            const unsigned aLo_base = xlo_s + stage * (XSTAGE * 2) + a_off;
            #pragma unroll
            for (int kk = 0; kk < 32; kk += 16) {
                unsigned Ah[2][4], Al[2][4];
                #pragma unroll
                for (int mf = 0; mf < 2; ++mf) {
                    unsigned off = (unsigned)(mf * 16 * XROW + kk) * 2;
                    ldsm_x4(aHi_base + off, Ah[mf][0], Ah[mf][1], Ah[mf][2], Ah[mf][3]);
                    ldsm_x4(aLo_base + off, Al[mf][0], Al[mf][1], Al[mf][2], Al[mf][3]);
                }
                int kabs = t * 32 + kk;
                #pragma unroll
                for (int nf = 0; nf < 4; ++nf) {
                    int n = warpN + nf * 8;
                    unsigned boff = (unsigned)((kabs + (lane & 15)) * WROW + n) * 2;
                    unsigned bh0, bh1, bl0, bl1;
                    ldsm_x2t(sptr(Whi) + boff, bh0, bh1);
                    ldsm_x2t(sptr(Wlo) + boff, bl0, bl1);
                    #pragma unroll
                    for (int mf = 0; mf < 2; ++mf) {
                        mma_bf16(c[mf][nf], Ah[mf][0], Ah[mf][1], Ah[mf][2], Ah[mf][3], bh0, bh1);
                        mma_bf16(c[mf][nf], Ah[mf][0], Ah[mf][1], Ah[mf][2], Ah[mf][3], bl0, bl1);
                        mma_bf16(c[mf][nf], Al[mf][0], Al[mf][1], Al[mf][2], Al[mf][3], bh0, bh1);
                    }
                }
            }
        }

        // ---- epilogue: bias, store h as fp16, fused scores ----
        #pragma unroll
        for (int mf = 0; mf < 2; ++mf) {
            #pragma unroll
            for (int half = 0; half < 2; ++half) {
                int lrow = warpM + mf * 16 + half * 8 + g;
                int grow = rowBase + lrow;
                float sd = 0.f, ss = 0.f;
                #pragma unroll
                for (int nf = 0; nf < 4; ++nf) {
                    int col = warpN + nf * 8 + tig * 2;
                    float o0 = c[mf][nf][half * 2 + 0] + __ldg(b + col);
                    float o1 = c[mf][nf][half * 2 + 1] + __ldg(b + col + 1);
                    if (grow < N) {
                        __half2 hh = __floats2half2_rn(o0, o1);
                        *(__half2*)(g_h16 + (size_t)grow * 128 + col) = hh;
                    }
                    sd += o0 * __ldg(a_w + col)       + o1 * __ldg(a_w + col + 1);
                    ss += o0 * __ldg(a_w + 128 + col) + o1 * __ldg(a_w + 129 + col);
                }
                #pragma unroll
                for (int o = 1; o <= 2; o <<= 1) {
                    sd += __shfl_xor_sync(0xFFFFFFFFu, sd, o);
                    ss += __shfl_xor_sync(0xFFFFFFFFu, ss, o);
                }
                if (tig == 0) {
                    sPartD[(wid & 3) * 128 + lrow] = sd;
                    sPartS[(wid & 3) * 128 + lrow] = ss;
                }
            }
        }
        __syncthreads();
        if (tid < 128) {
            int grow = rowBase + tid;
            if (grow < N) {
                g_sdst[grow] = sPartD[tid] + sPartD[128 + tid]
                             + sPartD[256 + tid] + sPartD[384 + tid];
                g_ssrc[grow] = sPartS[tid] + sPartS[128 + tid]
                             + sPartS[256 + tid] + sPartS[384 + tid];
            }
        }
        __syncthreads();   // sPart + X stage-0 safe for next tile
    }
}

// ---------------------------------------------------------------------------
// K2: row_ptr via lower_bound on sorted edge_dst
// ---------------------------------------------------------------------------
__global__ __launch_bounds__(256) void rowptr_kernel(const int* __restrict__ edge_dst,
                                                     int N, int E)
{
    int n = blockIdx.x * blockDim.x + threadIdx.x;
    if (n > N) return;
    int lo = 0, hi = E;
    while (lo < hi) {
        int mid = (lo + hi) >> 1;
        if (edge_dst[mid] < n) lo = mid + 1; else hi = mid;
    }
    g_rowptr[n] = lo;
}

// ---------------------------------------------------------------------------
// K3: warp-per-dst-node SINGLE-PASS segment softmax + aggregation.
//     fp16 h gather; (w,src) stashed in smem per chunk (1 broadcast LDS.64
//     per edge instead of 2 shfl); 4-edge batches with 4 LDGs in flight and
//     4 independent accumulator chains.
// ---------------------------------------------------------------------------
__global__ __launch_bounds__(256) void agg_kernel(const int* __restrict__ edge_src,
                                                  const float* __restrict__ a_b,
                                                  float* __restrict__ out, int N)
{
    __shared__ unsigned long long stash[8][32];

    int warp = (blockIdx.x * blockDim.x + threadIdx.x) >> 5;
    int ws   = (threadIdx.x >> 5);
    int lane = threadIdx.x & 31;
    if (warp >= N) return;

    int s = g_rowptr[warp];
    int e = g_rowptr[warp + 1];
    float4* op = (float4*)(out + (size_t)warp * 128);

    if (s == e) { op[lane] = make_float4(0.f, 0.f, 0.f, 0.f); return; }

    float base = g_sdst[warp] + a_b[0];

    float sum = 0.f;
    unsigned long long acc01[4] = {0ull, 0ull, 0ull, 0ull};
    unsigned long long acc23[4] = {0ull, 0ull, 0ull, 0ull};

    for (int chunk = s; chunk < e; chunk += 32) {
        int i = chunk + lane;
        int src = 0;
        float w = 0.f;
        if (i < e) {
            src = edge_src[i];
            float l = base + g_ssrc[src];
            l = (l >= 0.f) ? l : 0.01f * l;
            w = __expf(l);
        }
        sum += w;
        stash[ws][lane] = ((unsigned long long)(unsigned)src << 32)
                        | (unsigned long long)__float_as_uint(w);
        __syncwarp();

        int cnt = min(32, e - chunk);
        int j = 0;
        for (; j + 4 <= cnt; j += 4) {
            unsigned long long p0 = stash[ws][j + 0];
            unsigned long long p1 = stash[ws][j + 1];
            unsigned long long p2 = stash[ws][j + 2];
            unsigned long long p3 = stash[ws][j + 3];
            const uint2* r0 = (const uint2*)(g_h16 + ((size_t)(p0 >> 32)) * 128) + lane;
            const uint2* r1 = (const uint2*)(g_h16 + ((size_t)(p1 >> 32)) * 128) + lane;
            const uint2* r2 = (const uint2*)(g_h16 + ((size_t)(p2 >> 32)) * 128) + lane;
            const uint2* r3 = (const uint2*)(g_h16 + ((size_t)(p3 >> 32)) * 128) + lane;
            uint2 v0 = *r0;
            uint2 v1 = *r1;
            uint2 v2 = *r2;
            uint2 v3 = *r3;
            float w0 = __uint_as_float((unsigned)p0);
            float w1 = __uint_as_float((unsigned)p1);
            float w2 = __uint_as_float((unsigned)p2);
            float w3 = __uint_as_float((unsigned)p3);
            float2 a01 = __half22float2(*(__half2*)&v0.x);
            float2 a23 = __half22float2(*(__half2*)&v0.y);
            float2 b01 = __half22float2(*(__half2*)&v1.x);
            float2 b23 = __half22float2(*(__half2*)&v1.y);
            float2 c01 = __half22float2(*(__half2*)&v2.x);
            float2 c23 = __half22float2(*(__half2*)&v2.y);
            float2 d01 = __half22float2(*(__half2*)&v3.x);
            float2 d23 = __half22float2(*(__half2*)&v3.y);
            ffma2(acc01[0], pk2(w0, w0), pk2(a01.x, a01.y));
            ffma2(acc23[0], pk2(w0, w0), pk2(a23.x, a23.y));
            ffma2(acc01[1], pk2(w1, w1), pk2(b01.x, b01.y));
            ffma2(acc23[1], pk2(w1, w1), pk2(b23.x, b23.y));
            ffma2(acc01[2], pk2(w2, w2), pk2(c01.x, c01.y));
            ffma2(acc23[2], pk2(w2, w2), pk2(c23.x, c23.y));
            ffma2(acc01[3], pk2(w3, w3), pk2(d01.x, d01.y));
            ffma2(acc23[3], pk2(w3, w3), pk2(d23.x, d23.y));
        }
        for (; j < cnt; ++j) {
            unsigned long long p = stash[ws][j];
            const uint2* r = (const uint2*)(g_h16 + ((size_t)(p >> 32)) * 128) + lane;
            uint2 v = *r;
            float wj = __uint_as_float((unsigned)p);
            float2 f01 = __half22float2(*(__half2*)&v.x);
            float2 f23 = __half22float2(*(__half2*)&v.y);
            ffma2(acc01[j & 3], pk2(wj, wj), pk2(f01.x, f01.y));
            ffma2(acc23[j & 3], pk2(wj, wj), pk2(f23.x, f23.y));
        }
        __syncwarp();
    }
    #pragma unroll
    for (int o = 16; o; o >>= 1)
        sum += __shfl_xor_sync(0xFFFFFFFFu, sum, o);

    float inv = 1.0f / fmaxf(sum, 1e-16f);

    float r01a, r01b, r23a, r23b, t0, t1;
    upk2(acc01[0], r01a, r01b);
    upk2(acc01[1], t0, t1);    r01a += t0; r01b += t1;
    upk2(acc01[2], t0, t1);    r01a += t0; r01b += t1;
    upk2(acc01[3], t0, t1);    r01a += t0; r01b += t1;
    upk2(acc23[0], r23a, r23b);
    upk2(acc23[1], t0, t1);    r23a += t0; r23b += t1;
    upk2(acc23[2], t0, t1);    r23a += t0; r23b += t1;
    upk2(acc23[3], t0, t1);    r23a += t0; r23b += t1;

    op[lane] = make_float4(r01a * inv, r01b * inv, r23a * inv, r23b * inv);
}

// ---------------------------------------------------------------------------
extern "C" void kernel_launch(void* const* d_in, const int* in_sizes, int n_in,
                              void* d_out, int out_size)
{
    const float* x        = (const float*)d_in[0];
    const int*   edge_src = (const int*)d_in[1];
    const int*   edge_dst = (const int*)d_in[2];
    const float* W        = (const float*)d_in[3];
    const float* b        = (const float*)d_in[4];
    const float* a_w      = (const float*)d_in[5];
    const float* a_b      = (const float*)d_in[6];
    float*       out      = (float*)d_out;

    const int N = in_sizes[0] / DOUT;   // 50000
    const int E = in_sizes[1];          // 800000

    const int SMEM_BYTES = 114688;
    cudaFuncSetAttribute(gemm_score_kernel,
                         cudaFuncAttributeMaxDynamicSharedMemorySize, SMEM_BYTES);

    gemm_score_kernel<<<148, 512, SMEM_BYTES>>>(x, W, b, a_w, N);
    rowptr_kernel<<<(N + 1 + 255) / 256, 256>>>(edge_dst, N, E);
    agg_kernel<<<(N + 7) / 8, 256>>>(edge_src, a_b, out, N);
}